// round 10
// baseline (speedup 1.0000x reference)
#include <cuda_runtime.h>
#include <cuda_fp16.h>
#include <cstdint>

// MoE SwiGLU, fp16 tensor cores (mma.m16n8k16, fp32 accum).
// R8 fix: cp.async dst rows must be 16B-aligned -> fp32 staging strides
// padded to 16B multiples (G1_RS 18->20, G2_BS 66->68).
//   - cp.async 4-deep fp32 smem ring (bytes-in-flight fix per Little's law)
//   - MMA fragments built straight from fp32 smem via LDS + cvt
//   1) route_kernel : bucket 1024 (token,slot) pairs by expert
//   2) gemm1_kernel : hbuf(fp16) = silu(x.w1[e]^T) * (x.w3[e]^T)
//   3) gemm2_kernel : out = hbuf . w2[e]   (fp32 out)

namespace {
constexpr int kE = 8;
constexpr int kTOPK = 2;
constexpr int kH = 2816;
constexpr int kD = 1024;
constexpr int NP = 1024;

constexpr int S = 4;                    // pipeline depth

constexpr int G1_NT_H = kH / 128;       // 22
constexpr int G1_RS = 20;               // fp32 row stride (16 + 4 pad, 80B = 16B-mult)
constexpr int G2_NT_D = kD / 64;        // 16
constexpr int G2_AS = 40;               // A fp16 row stride (32 + 8 pad, 80B)
constexpr int G2_BS = 68;               // B fp32 row stride (64 + 4 pad, 272B = 16B-mult)

constexpr size_t G1_SMEM = (size_t)3 * S * 128 * G1_RS * 4 + 512;   // ~120.5 KB
constexpr size_t G2_SMEM = (size_t)S * 128 * G2_AS * 2
                         + (size_t)S * 32 * G2_BS * 4 + 512;        // ~74.5 KB
}

__device__ int    g_off[kE + 1];
__device__ int    g_pairs[NP];
__device__ __half g_hbuf[(size_t)NP * kH];   // 5.77 MB fp16 intermediate

// ---------------------------------------------------------------------------
// helpers
// ---------------------------------------------------------------------------
__device__ __forceinline__ uint32_t s2u(const void* p) {
    return (uint32_t)__cvta_generic_to_shared(p);
}
__device__ __forceinline__ void cp_async16(void* dst, const void* src) {
    asm volatile("cp.async.cg.shared.global [%0], [%1], 16;"
                 :: "r"(s2u(dst)), "l"(src));
}
__device__ __forceinline__ void cp_commit() {
    asm volatile("cp.async.commit_group;");
}
template <int N>
__device__ __forceinline__ void cp_wait() {
    asm volatile("cp.async.wait_group %0;" :: "n"(N));
}
__device__ __forceinline__ void ldsm_x4(uint32_t r[4], uint32_t addr) {
    asm volatile("ldmatrix.sync.aligned.m8n8.x4.shared.b16 {%0,%1,%2,%3}, [%4];"
                 : "=r"(r[0]), "=r"(r[1]), "=r"(r[2]), "=r"(r[3]) : "r"(addr));
}
__device__ __forceinline__ void mma16816(float c[4], const uint32_t a[4],
                                         uint32_t b0, uint32_t b1) {
    asm volatile(
        "mma.sync.aligned.m16n8k16.row.col.f32.f16.f16.f32 "
        "{%0,%1,%2,%3},{%4,%5,%6,%7},{%8,%9},{%0,%1,%2,%3};"
        : "+f"(c[0]), "+f"(c[1]), "+f"(c[2]), "+f"(c[3])
        : "r"(a[0]), "r"(a[1]), "r"(a[2]), "r"(a[3]), "r"(b0), "r"(b1));
}
__device__ __forceinline__ uint32_t h2u(__half2 h) {
    return *reinterpret_cast<uint32_t*>(&h);
}
__device__ __forceinline__ uint32_t cvt2(const float* p) {
    float2 v = *(const float2*)p;
    return h2u(__floats2half2_rn(v.x, v.y));
}
__device__ __forceinline__ uint32_t cvt2s(float a, float b) {
    return h2u(__floats2half2_rn(a, b));
}
__device__ __forceinline__ float silu(float z) {
    return z / (1.0f + __expf(-z));
}

// ---------------------------------------------------------------------------
// Routing (int32/int64 dtype auto-detect; validated R3-R5)
// ---------------------------------------------------------------------------
__global__ void route_kernel(const void* __restrict__ eidx_raw) {
    __shared__ int cnt[kE];
    __shared__ int cur[kE];
    __shared__ int not64;
    int tid = threadIdx.x;
    if (tid < kE) cnt[tid] = 0;
    if (tid == 0) not64 = 0;
    __syncthreads();

    const long long* p64 = (const long long*)eidx_raw;
    if (tid < NP / 2) {
        long long v = p64[tid];
        if (v < 0 || v >= kE) not64 = 1;
    }
    __syncthreads();

    int e = not64 ? ((const int*)eidx_raw)[tid] : (int)p64[tid];

    atomicAdd(&cnt[e], 1);
    __syncthreads();
    if (tid == 0) {
        int o = 0;
        for (int i = 0; i < kE; i++) { g_off[i] = o; cur[i] = o; o += cnt[i]; }
        g_off[kE] = o;
    }
    __syncthreads();
    int p = atomicAdd(&cur[e], 1);
    g_pairs[p] = tid;
}

// ---------------------------------------------------------------------------
// GEMM1 + SwiGLU. 256 threads, 8 warps: 2(m,64) x 4(n,32). 64 stages of k16.
// grid.x = 2 strips * 22 htiles * 8 experts = 352.
// ---------------------------------------------------------------------------
__global__ __launch_bounds__(256, 1)
void gemm1_kernel(const float* __restrict__ x,
                  const float* __restrict__ w1,
                  const float* __restrict__ w3) {
    extern __shared__ char smem_raw[];
    float (*Xs) [128][G1_RS] = (float(*)[128][G1_RS])smem_raw;
    float (*W1s)[128][G1_RS] = (float(*)[128][G1_RS])(smem_raw + (size_t)S*128*G1_RS*4);
    float (*W3s)[128][G1_RS] = (float(*)[128][G1_RS])(smem_raw + (size_t)2*S*128*G1_RS*4);
    int* toks = (int*)(smem_raw + (size_t)3*S*128*G1_RS*4);

    const int bx    = blockIdx.x;
    const int strip = bx & 1;
    const int ht    = (bx >> 1) % G1_NT_H;
    const int e     = bx / (2 * G1_NT_H);
    const int hb    = ht * 128;
    const int base  = g_off[e];
    const int nt    = g_off[e + 1] - base;

    const int tid  = threadIdx.x;
    const int lane = tid & 31;
    const int wid  = tid >> 5;
    const int wm   = wid & 1;
    const int wn   = wid >> 1;

    const float* w1e = w1 + ((size_t)e * kH + hb) * kD;
    const float* w3e = w3 + ((size_t)e * kH + hb) * kD;

    const int NST = kD / 16;   // 64
    const int lr = lane >> 2;
    const int lc = (lane & 3) * 2;

    for (int t0 = strip * 128; t0 < nt; t0 += 256) {
        const int ntt = min(128, nt - t0);

        if (tid < 128)
            toks[tid] = g_pairs[base + t0 + min(tid, ntt - 1)] / kTOPK;
        __syncthreads();

        auto issue = [&](int ks) {
            int slot = ks & (S - 1);
            int d0 = ks * 16;
            #pragma unroll
            for (int r = 0; r < 2; r++) {
                int i = tid + r * 256;
                int m = i >> 2, k4 = (i & 3) * 4;
                cp_async16(&Xs [slot][m][k4], &x  [(size_t)toks[m] * kD + d0 + k4]);
                cp_async16(&W1s[slot][m][k4], &w1e[(size_t)m       * kD + d0 + k4]);
                cp_async16(&W3s[slot][m][k4], &w3e[(size_t)m       * kD + d0 + k4]);
            }
        };

        #pragma unroll
        for (int s = 0; s < S - 1; s++) { issue(s); cp_commit(); }

        float acc1[4][4][4], acc3[4][4][4];
        #pragma unroll
        for (int mt = 0; mt < 4; mt++)
            #pragma unroll
            for (int j = 0; j < 4; j++)
                #pragma unroll
                for (int q = 0; q < 4; q++) { acc1[mt][j][q] = 0.f; acc3[mt][j][q] = 0.f; }

        for (int ks = 0; ks < NST; ks++) {
            cp_wait<S - 2>();
            __syncthreads();
            if (ks + S - 1 < NST) issue(ks + S - 1);
            cp_commit();

            const int slot = ks & (S - 1);
            const float (*X)[G1_RS]  = Xs [slot];
            const float (*W1)[G1_RS] = W1s[slot];
            const float (*W3)[G1_RS] = W3s[slot];

            uint32_t a[4][4];
            #pragma unroll
            for (int mt = 0; mt < 4; mt++) {
                int r = wm * 64 + mt * 16 + lr;
                a[mt][0] = cvt2(&X[r    ][lc    ]);
                a[mt][1] = cvt2(&X[r + 8][lc    ]);
                a[mt][2] = cvt2(&X[r    ][lc + 8]);
                a[mt][3] = cvt2(&X[r + 8][lc + 8]);
            }
            #pragma unroll
            for (int j = 0; j < 4; j++) {
                int n = wn * 32 + j * 8 + lr;
                uint32_t b1lo = cvt2(&W1[n][lc]), b1hi = cvt2(&W1[n][lc + 8]);
                uint32_t b3lo = cvt2(&W3[n][lc]), b3hi = cvt2(&W3[n][lc + 8]);
                #pragma unroll
                for (int mt = 0; mt < 4; mt++) {
                    mma16816(acc1[mt][j], a[mt], b1lo, b1hi);
                    mma16816(acc3[mt][j], a[mt], b3lo, b3hi);
                }
            }
        }

        // epilogue: silu(h1)*h3 -> g_hbuf (fp16)
        #pragma unroll
        for (int mt = 0; mt < 4; mt++) {
            int row0 = wm * 64 + mt * 16 + (lane >> 2);
            #pragma unroll
            for (int j = 0; j < 4; j++) {
                int col = hb + wn * 32 + j * 8 + (lane & 3) * 2;
                if (row0 < ntt) {
                    float v0 = silu(acc1[mt][j][0]) * acc3[mt][j][0];
                    float v1 = silu(acc1[mt][j][1]) * acc3[mt][j][1];
                    *(__half2*)&g_hbuf[(size_t)(base + t0 + row0) * kH + col] =
                        __floats2half2_rn(v0, v1);
                }
                if (row0 + 8 < ntt) {
                    float v0 = silu(acc1[mt][j][2]) * acc3[mt][j][2];
                    float v1 = silu(acc1[mt][j][3]) * acc3[mt][j][3];
                    *(__half2*)&g_hbuf[(size_t)(base + t0 + row0 + 8) * kH + col] =
                        __floats2half2_rn(v0, v1);
                }
            }
        }
        __syncthreads();
    }
}

// ---------------------------------------------------------------------------
// GEMM2. 256 threads, 8 warps: 4(m,32) x 2(n,32). 88 stages of k32.
// grid.x = 2 strips * 16 dtiles * 8 experts = 256.
// ---------------------------------------------------------------------------
__global__ __launch_bounds__(256, 1)
void gemm2_kernel(const float* __restrict__ w2, float* __restrict__ out) {
    extern __shared__ char smem_raw[];
    __half (*As)[128][G2_AS] = (__half(*)[128][G2_AS])smem_raw;
    float  (*Bs)[32][G2_BS]  = (float(*)[32][G2_BS])(smem_raw + (size_t)S*128*G2_AS*2);
    int* prs = (int*)(smem_raw + (size_t)S*128*G2_AS*2 + (size_t)S*32*G2_BS*4);

    const int bx    = blockIdx.x;
    const int strip = bx & 1;
    const int dt    = (bx >> 1) % G2_NT_D;
    const int e     = bx / (2 * G2_NT_D);
    const int ib    = dt * 64;
    const int base  = g_off[e];
    const int nt    = g_off[e + 1] - base;

    const int tid  = threadIdx.x;
    const int lane = tid & 31;
    const int wid  = tid >> 5;
    const int wm   = wid & 3;
    const int wn   = wid >> 2;

    const float* w2e = w2 + (size_t)e * kH * kD + ib;

    const int lrow = lane & 15;
    const int lcol = (lane >> 4) * 8;
    const int lr   = lane >> 2;
    const int lc   = (lane & 3) * 2;

    const int NST = kH / 32;   // 88

    for (int t0 = strip * 128; t0 < nt; t0 += 256) {
        const int ntt = min(128, nt - t0);

        if (tid < 128)
            prs[tid] = g_pairs[base + t0 + min(tid, ntt - 1)];
        __syncthreads();

        auto issue = [&](int ks) {
            int slot = ks & (S - 1);
            int h0 = ks * 32;
            #pragma unroll
            for (int r = 0; r < 2; r++) {
                int i = tid + r * 256;
                int m = i >> 2, c8 = (i & 3) * 8;
                int arow = min(m, ntt - 1);
                cp_async16(&As[slot][m][c8],
                           &g_hbuf[(size_t)(base + t0 + arow) * kH + h0 + c8]);
                int h = i >> 4, d4 = (i & 15) * 4;
                cp_async16(&Bs[slot][h][d4], &w2e[(size_t)(h0 + h) * kD + d4]);
            }
        };

        #pragma unroll
        for (int s = 0; s < S - 1; s++) { issue(s); cp_commit(); }

        float acc[2][4][4];
        #pragma unroll
        for (int mt = 0; mt < 2; mt++)
            #pragma unroll
            for (int j = 0; j < 4; j++)
                #pragma unroll
                for (int q = 0; q < 4; q++) acc[mt][j][q] = 0.f;

        for (int ks = 0; ks < NST; ks++) {
            cp_wait<S - 2>();
            __syncthreads();
            if (ks + S - 1 < NST) issue(ks + S - 1);
            cp_commit();

            const int slot = ks & (S - 1);
            const float (*B)[G2_BS] = Bs[slot];

            #pragma unroll
            for (int kk = 0; kk < 2; kk++) {
                uint32_t a[2][4];
                #pragma unroll
                for (int mt = 0; mt < 2; mt++)
                    ldsm_x4(a[mt], s2u(&As[slot][wm * 32 + mt * 16 + lrow][kk * 16 + lcol]));
                #pragma unroll
                for (int j = 0; j < 4; j++) {
                    int n  = wn * 32 + j * 8 + lr;
                    int k0 = kk * 16 + lc;
                    uint32_t b0 = cvt2s(B[k0    ][n], B[k0 + 1][n]);
                    uint32_t b1 = cvt2s(B[k0 + 8][n], B[k0 + 9][n]);
                    #pragma unroll
                    for (int mt = 0; mt < 2; mt++)
                        mma16816(acc[mt][j], a[mt], b0, b1);
                }
            }
        }

        // epilogue: fp32 stores to out[pair][d]
        #pragma unroll
        for (int mt = 0; mt < 2; mt++) {
            int row0 = wm * 32 + mt * 16 + (lane >> 2);
            #pragma unroll
            for (int j = 0; j < 4; j++) {
                int col = ib + wn * 32 + j * 8 + (lane & 3) * 2;
                if (row0 < ntt) {
                    float2 v = { acc[mt][j][0], acc[mt][j][1] };
                    *(float2*)&out[(size_t)prs[row0] * kD + col] = v;
                }
                if (row0 + 8 < ntt) {
                    float2 v = { acc[mt][j][2], acc[mt][j][3] };
                    *(float2*)&out[(size_t)prs[row0 + 8] * kD + col] = v;
                }
            }
        }
        __syncthreads();
    }
}

// ---------------------------------------------------------------------------
extern "C" void kernel_launch(void* const* d_in, const int* in_sizes, int n_in,
                              void* d_out, int out_size) {
    const float* x    = (const float*)d_in[0];
    const void*  eidx = d_in[1];
    const float* w1   = (const float*)d_in[2];
    const float* w2   = (const float*)d_in[3];
    const float* w3   = (const float*)d_in[4];
    float*       out  = (float*)d_out;

    // Unconditional (idempotent, immediate, not captured into the graph).
    cudaFuncSetAttribute(gemm1_kernel,
        cudaFuncAttributeMaxDynamicSharedMemorySize, (int)G1_SMEM);
    cudaFuncSetAttribute(gemm2_kernel,
        cudaFuncAttributeMaxDynamicSharedMemorySize, (int)G2_SMEM);

    route_kernel<<<1, NP>>>(eidx);
    gemm1_kernel<<<2 * G1_NT_H * kE, 256, G1_SMEM>>>(x, w1, w3);
    gemm2_kernel<<<2 * G2_NT_D * kE, 256, G2_SMEM>>>(w2, out);
}

// round 13
// speedup vs baseline: 2.1735x; 2.1735x over previous
#include <cuda_runtime.h>
#include <cuda_fp16.h>
#include <cstdint>

// MoE SwiGLU via fp16 tensor cores (mma.m16n8k16, fp32 accum), fused
// fp32->fp16 conversion in the smem load path. Weights stay fp32 in HBM.
// R12: 2 CTAs/SM (independent barriers -> latency overlap). gemm1 redesigned
// BM=128/BN=64/BK=32 to fit 128 regs; gemm2 is R4-verbatim + launch_bounds 2.
//   1) route_kernel : bucket 1024 (token,slot) pairs by expert
//   2) gemm1_kernel : hbuf(fp16) = silu(x.w1[e]^T) * (x.w3[e]^T)
//   3) gemm2_kernel : out = hbuf . w2[e]   (fp32 out)

namespace {
constexpr int kE = 8;
constexpr int kTOPK = 2;
constexpr int kH = 2816;
constexpr int kD = 1024;
constexpr int NP = 1024;

// GEMM1: BM=128 tokens, BN=64 h (x2 matrices), BK=32
constexpr int G1_NT_H = kH / 64;        // 44 h-tiles
constexpr int G1_XS = 40;               // smem row stride fp16 (32+8 pad) — proven
// GEMM2: BM=128 tokens, BN=64 d, BK=32 (R4 verbatim)
constexpr int G2_NT_D = kD / 64;        // 16 d-tiles
constexpr int G2_AS = 40;               // A row stride fp16 (32+8 pad)
constexpr int G2_BS = 72;               // B row stride fp16 (64+8 pad)
}

__device__ int    g_off[kE + 1];
__device__ int    g_pairs[NP];
__device__ __half g_hbuf[(size_t)NP * kH];   // 5.77 MB fp16 intermediate

// ---------------------------------------------------------------------------
// helpers
// ---------------------------------------------------------------------------
__device__ __forceinline__ uint32_t s2u(const void* p) {
    return (uint32_t)__cvta_generic_to_shared(p);
}
__device__ __forceinline__ void ldsm_x4(uint32_t r[4], uint32_t addr) {
    asm volatile("ldmatrix.sync.aligned.m8n8.x4.shared.b16 {%0,%1,%2,%3}, [%4];"
                 : "=r"(r[0]), "=r"(r[1]), "=r"(r[2]), "=r"(r[3]) : "r"(addr));
}
__device__ __forceinline__ void ldsm_x4_t(uint32_t r[4], uint32_t addr) {
    asm volatile("ldmatrix.sync.aligned.m8n8.x4.trans.shared.b16 {%0,%1,%2,%3}, [%4];"
                 : "=r"(r[0]), "=r"(r[1]), "=r"(r[2]), "=r"(r[3]) : "r"(addr));
}
__device__ __forceinline__ void mma16816(float c[4], const uint32_t a[4],
                                         uint32_t b0, uint32_t b1) {
    asm volatile(
        "mma.sync.aligned.m16n8k16.row.col.f32.f16.f16.f32 "
        "{%0,%1,%2,%3},{%4,%5,%6,%7},{%8,%9},{%0,%1,%2,%3};"
        : "+f"(c[0]), "+f"(c[1]), "+f"(c[2]), "+f"(c[3])
        : "r"(a[0]), "r"(a[1]), "r"(a[2]), "r"(a[3]), "r"(b0), "r"(b1));
}
__device__ __forceinline__ uint32_t h2u(__half2 h) {
    return *reinterpret_cast<uint32_t*>(&h);
}
__device__ __forceinline__ uint2 cvt4(float4 v) {
    uint2 u = { h2u(__floats2half2_rn(v.x, v.y)),
                h2u(__floats2half2_rn(v.z, v.w)) };
    return u;
}
__device__ __forceinline__ float silu(float z) {
    return z / (1.0f + __expf(-z));
}

// ---------------------------------------------------------------------------
// Routing (int32/int64 dtype auto-detect; validated R3+)
// ---------------------------------------------------------------------------
__global__ void route_kernel(const void* __restrict__ eidx_raw) {
    __shared__ int cnt[kE];
    __shared__ int cur[kE];
    __shared__ int not64;
    int tid = threadIdx.x;
    if (tid < kE) cnt[tid] = 0;
    if (tid == 0) not64 = 0;
    __syncthreads();

    const long long* p64 = (const long long*)eidx_raw;
    if (tid < NP / 2) {
        long long v = p64[tid];
        if (v < 0 || v >= kE) not64 = 1;
    }
    __syncthreads();

    int e = not64 ? ((const int*)eidx_raw)[tid] : (int)p64[tid];

    atomicAdd(&cnt[e], 1);
    __syncthreads();
    if (tid == 0) {
        int o = 0;
        for (int i = 0; i < kE; i++) { g_off[i] = o; cur[i] = o; o += cnt[i]; }
        g_off[kE] = o;
    }
    __syncthreads();
    int p = atomicAdd(&cur[e], 1);
    g_pairs[p] = tid;
}

// ---------------------------------------------------------------------------
// GEMM1 + SwiGLU. 256 threads, 8 warps: 2(m,64) x 4(n,16). 32 stages of k32.
// grid.x = 2 strips * 44 htiles * 8 experts = 704.  2 CTAs/SM.
// Block tile: 128 tokens x 64 h for BOTH w1 and w3.
// ---------------------------------------------------------------------------
__global__ __launch_bounds__(256, 2)
void gemm1_kernel(const float* __restrict__ x,
                  const float* __restrict__ w1,
                  const float* __restrict__ w3) {
    __shared__ __half Xs [2][128][G1_XS];
    __shared__ __half W1s[2][64][G1_XS];
    __shared__ __half W3s[2][64][G1_XS];
    __shared__ int    toks[128];

    const int bx    = blockIdx.x;
    const int strip = bx & 1;
    const int ht    = (bx >> 1) % G1_NT_H;
    const int e     = bx / (2 * G1_NT_H);
    const int hb    = ht * 64;
    const int base  = g_off[e];
    const int nt    = g_off[e + 1] - base;

    const int tid  = threadIdx.x;
    const int lane = tid & 31;
    const int wid  = tid >> 5;
    const int wm   = wid & 1;       // 2 m-warps (64 rows each)
    const int wn   = wid >> 1;      // 4 n-warps (16 cols each)

    const float* w1e = w1 + ((size_t)e * kH + hb) * kD;
    const float* w3e = w3 + ((size_t)e * kH + hb) * kD;

    const int lrow = lane & 15;
    const int lcol = (lane >> 4) * 8;

    const int NST = kD / 32;   // 32

    for (int t0 = strip * 128; t0 < nt; t0 += 256) {
        const int ntt = min(128, nt - t0);

        __syncthreads();
        if (tid < 128)
            toks[tid] = g_pairs[base + t0 + min(tid, ntt - 1)] / kTOPK;
        __syncthreads();

        float4 sx[4], s1[2], s3[2];
        auto ldg_stage = [&](int d0) {
            #pragma unroll
            for (int r = 0; r < 4; r++) {            // X: 128 x 32 fp32, 4/thread
                int c = tid + r * 256;
                int m = c >> 3, k4 = (c & 7) * 4;
                sx[r] = *(const float4*)&x[(size_t)toks[m] * kD + d0 + k4];
            }
            #pragma unroll
            for (int r = 0; r < 2; r++) {            // W: 64 x 32 fp32, 2/thread each
                int c = tid + r * 256;
                int n = c >> 3, k4 = (c & 7) * 4;
                s1[r] = *(const float4*)&w1e[(size_t)n * kD + d0 + k4];
                s3[r] = *(const float4*)&w3e[(size_t)n * kD + d0 + k4];
            }
        };
        auto sts_stage = [&](int s) {
            #pragma unroll
            for (int r = 0; r < 4; r++) {
                int c = tid + r * 256;
                int m = c >> 3, k4 = (c & 7) * 4;
                *(uint2*)&Xs[s][m][k4] = cvt4(sx[r]);
            }
            #pragma unroll
            for (int r = 0; r < 2; r++) {
                int c = tid + r * 256;
                int n = c >> 3, k4 = (c & 7) * 4;
                *(uint2*)&W1s[s][n][k4] = cvt4(s1[r]);
                *(uint2*)&W3s[s][n][k4] = cvt4(s3[r]);
            }
        };

        ldg_stage(0);
        sts_stage(0);
        __syncthreads();

        float acc1[4][2][4], acc3[4][2][4];
        #pragma unroll
        for (int mt = 0; mt < 4; mt++)
            #pragma unroll
            for (int j = 0; j < 2; j++)
                #pragma unroll
                for (int q = 0; q < 4; q++) { acc1[mt][j][q] = 0.f; acc3[mt][j][q] = 0.f; }

        for (int ks = 0; ks < NST; ks++) {
            int s = ks & 1;
            if (ks + 1 < NST) ldg_stage((ks + 1) * 32);

            #pragma unroll
            for (int kk = 0; kk < 2; kk++) {
                uint32_t a[4][4], b1[4], b3[4];
                #pragma unroll
                for (int mt = 0; mt < 4; mt++)
                    ldsm_x4(a[mt], s2u(&Xs[s][wm * 64 + mt * 16 + lrow][kk * 16 + lcol]));
                ldsm_x4(b1, s2u(&W1s[s][wn * 16 + lrow][kk * 16 + lcol]));
                ldsm_x4(b3, s2u(&W3s[s][wn * 16 + lrow][kk * 16 + lcol]));
                #pragma unroll
                for (int mt = 0; mt < 4; mt++)
                    #pragma unroll
                    for (int j = 0; j < 2; j++) {
                        mma16816(acc1[mt][j], a[mt], b1[j], b1[2 + j]);
                        mma16816(acc3[mt][j], a[mt], b3[j], b3[2 + j]);
                    }
            }

            if (ks + 1 < NST) sts_stage(s ^ 1);
            __syncthreads();
        }

        // epilogue: silu(h1)*h3 -> g_hbuf (fp16)
        #pragma unroll
        for (int mt = 0; mt < 4; mt++) {
            int row0 = wm * 64 + mt * 16 + (lane >> 2);
            #pragma unroll
            for (int j = 0; j < 2; j++) {
                int col = hb + wn * 16 + j * 8 + (lane & 3) * 2;
                if (row0 < ntt) {
                    float v0 = silu(acc1[mt][j][0]) * acc3[mt][j][0];
                    float v1 = silu(acc1[mt][j][1]) * acc3[mt][j][1];
                    *(__half2*)&g_hbuf[(size_t)(base + t0 + row0) * kH + col] =
                        __floats2half2_rn(v0, v1);
                }
                if (row0 + 8 < ntt) {
                    float v0 = silu(acc1[mt][j][2]) * acc3[mt][j][2];
                    float v1 = silu(acc1[mt][j][3]) * acc3[mt][j][3];
                    *(__half2*)&g_hbuf[(size_t)(base + t0 + row0 + 8) * kH + col] =
                        __floats2half2_rn(v0, v1);
                }
            }
        }
    }
}

// ---------------------------------------------------------------------------
// GEMM2 — R4 verbatim, occupancy 2. 256 threads, 8 warps: 4(m,32) x 2(n,32).
// grid.x = 2 strips * 16 dtiles * 8 experts = 256. 88 stages of k32.
// ---------------------------------------------------------------------------
__global__ __launch_bounds__(256, 2)
void gemm2_kernel(const float* __restrict__ w2, float* __restrict__ out) {
    __shared__ __half As[2][128][G2_AS];
    __shared__ __half Bs[2][32][G2_BS];
    __shared__ int    prs[128];

    const int bx    = blockIdx.x;
    const int strip = bx & 1;
    const int dt    = (bx >> 1) % G2_NT_D;
    const int e     = bx / (2 * G2_NT_D);
    const int ib    = dt * 64;
    const int base  = g_off[e];
    const int nt    = g_off[e + 1] - base;

    const int tid  = threadIdx.x;
    const int lane = tid & 31;
    const int wid  = tid >> 5;
    const int wm   = wid & 3;
    const int wn   = wid >> 2;

    const float* w2e = w2 + (size_t)e * kH * kD + ib;

    const int lrow = lane & 15;
    const int lcol = (lane >> 4) * 8;
    const int ti   = lane >> 3;
    const int trow = (ti >> 1) * 8 + (lane & 7);
    const int tcol = (ti & 1) * 8;

    for (int t0 = strip * 128; t0 < nt; t0 += 256) {
        const int ntt = min(128, nt - t0);

        __syncthreads();
        if (tid < 128)
            prs[tid] = g_pairs[base + t0 + min(tid, ntt - 1)];
        __syncthreads();

        uint4  stA[2];
        float4 stB[2];
        auto ldg_stage = [&](int h0) {
            #pragma unroll
            for (int r = 0; r < 2; r++) {
                int i = tid + r * 256;
                int m = i >> 2, c8 = i & 3;
                int tc = min(m, ntt - 1);
                stA[r] = *(const uint4*)&g_hbuf[(size_t)(base + t0 + tc) * kH + h0 + c8 * 8];
                int h = i >> 4, d4 = i & 15;
                stB[r] = *(const float4*)&w2e[(size_t)(h0 + h) * kD + d4 * 4];
            }
        };
        auto sts_stage = [&](int s) {
            #pragma unroll
            for (int r = 0; r < 2; r++) {
                int i = tid + r * 256;
                int m = i >> 2, c8 = i & 3;
                *(uint4*)&As[s][m][c8 * 8] = stA[r];
                int h = i >> 4, d4 = i & 15;
                float4 v = stB[r];
                uint2 u = { h2u(__floats2half2_rn(v.x, v.y)),
                            h2u(__floats2half2_rn(v.z, v.w)) };
                *(uint2*)&Bs[s][h][d4 * 4] = u;
            }
        };

        ldg_stage(0);
        sts_stage(0);
        __syncthreads();

        float acc[2][4][4];
        #pragma unroll
        for (int mt = 0; mt < 2; mt++)
            #pragma unroll
            for (int ntl = 0; ntl < 4; ntl++)
                #pragma unroll
                for (int q = 0; q < 4; q++) acc[mt][ntl][q] = 0.f;

        const int NST = kH / 32;   // 88
        for (int ks = 0; ks < NST; ks++) {
            int s = ks & 1;
            if (ks + 1 < NST) ldg_stage((ks + 1) * 32);

            #pragma unroll
            for (int kk = 0; kk < 2; kk++) {
                uint32_t a[2][4], b[2][4];
                #pragma unroll
                for (int mt = 0; mt < 2; mt++)
                    ldsm_x4(a[mt], s2u(&As[s][wm * 32 + mt * 16 + lrow][kk * 16 + lcol]));
                #pragma unroll
                for (int g2 = 0; g2 < 2; g2++)
                    ldsm_x4_t(b[g2], s2u(&Bs[s][kk * 16 + trow][wn * 32 + g2 * 16 + tcol]));
                #pragma unroll
                for (int mt = 0; mt < 2; mt++)
                    #pragma unroll
                    for (int ntl = 0; ntl < 4; ntl++) {
                        int g2 = ntl >> 1, sub = ntl & 1;
                        mma16816(acc[mt][ntl], a[mt], b[g2][sub], b[g2][2 + sub]);
                    }
            }

            if (ks + 1 < NST) sts_stage(s ^ 1);
            __syncthreads();
        }

        #pragma unroll
        for (int mt = 0; mt < 2; mt++) {
            int row0 = wm * 32 + mt * 16 + (lane >> 2);
            #pragma unroll
            for (int ntl = 0; ntl < 4; ntl++) {
                int col = ib + wn * 32 + ntl * 8 + (lane & 3) * 2;
                if (row0 < ntt) {
                    float2 v = { acc[mt][ntl][0], acc[mt][ntl][1] };
                    *(float2*)&out[(size_t)prs[row0] * kD + col] = v;
                }
                if (row0 + 8 < ntt) {
                    float2 v = { acc[mt][ntl][2], acc[mt][ntl][3] };
                    *(float2*)&out[(size_t)prs[row0 + 8] * kD + col] = v;
                }
            }
        }
    }
}

// ---------------------------------------------------------------------------
extern "C" void kernel_launch(void* const* d_in, const int* in_sizes, int n_in,
                              void* d_out, int out_size) {
    const float* x    = (const float*)d_in[0];
    const void*  eidx = d_in[1];
    const float* w1   = (const float*)d_in[2];
    const float* w2   = (const float*)d_in[3];
    const float* w3   = (const float*)d_in[4];
    float*       out  = (float*)d_out;

    route_kernel<<<1, NP>>>(eidx);
    gemm1_kernel<<<2 * G1_NT_H * kE, 256>>>(x, w1, w3);
    gemm2_kernel<<<2 * G2_NT_D * kE, 256>>>(w2, out);
}